// round 10
// baseline (speedup 1.0000x reference)
#include <cuda_runtime.h>

typedef unsigned long long ull;

#define BATCH 32
#define NATOM 128
#define HH 64
#define WW 64
#define OH 57
#define SPP (OH*OH)           // 3249
#define NPS (NATOM*SPP)       // 415872
#define KSEL 256
#define NAL 17
#define CAP 2048
#define NBINS 4096
#define IMGPIX (HH*WW)        // 4096
#define NW32 (NPS/2)          // 207936 u32 key-pairs per sample
#define NV16 (NPS/8)          // 51984 uint4 per sample
#define HCHUNK 1024           // uint4 per collect chunk (51 chunks)

// ---------------- device state ----------------
__device__ float d_R[BATCH*IMGPIX];
__device__ float d_g[BATCH*NPS];              // ~53 MB dense gradient
__device__ unsigned d_gh[BATCH*NW32];         // ~26.6 MB u16 key pairs (interleaved atom-pairs)
__device__ int   d_hist[BATCH*NBINS];
__device__ int   d_ccnt[BATCH];
__device__ int   d_cpos[BATCH*CAP];
__device__ float d_cg[BATCH*CAP];
__device__ float d_cx[BATCH*CAP];
__device__ int   d_selp[NAL*BATCH*KSEL];
__device__ float d_selv[NAL*BATCH*KSEL];
__device__ float d_errp[NAL*BATCH];
__device__ float d_l2p[BATCH];
__device__ int   d_supp[BATCH*KSEL];
__device__ int   d_nsup[BATCH];

__device__ __forceinline__ int binof(float g) {
    return (int)((__float_as_uint(g) & 0x7fffffffu) >> 19);
}

// inclusive suffix sum over blockDim.x per-thread values
__device__ __forceinline__ int suffix_scan(int v, volatile int* wtmp, int nwarp) {
    int lane = threadIdx.x & 31, wid = threadIdx.x >> 5;
    int x = v;
    #pragma unroll
    for (int off = 1; off < 32; off <<= 1) {
        int u = __shfl_down_sync(0xffffffffu, x, off);
        if (lane + off < 32) x += u;
    }
    if (lane == 0) wtmp[wid] = x;
    __syncthreads();
    int add = 0;
    for (int j = wid + 1; j < nwarp; j++) add += wtmp[j];
    return x + add;
}

// ---------------- kernels ----------------

__global__ void k_init(float* __restrict__ X) {
    float4* X4 = (float4*)X;
    int stride = gridDim.x * blockDim.x;
    float4 z = make_float4(0.f, 0.f, 0.f, 0.f);
    for (int i = blockIdx.x * blockDim.x + threadIdx.x; i < BATCH*NPS/4; i += stride)
        X4[i] = z;
    if (blockIdx.x == 0 && threadIdx.x < BATCH) d_nsup[threadIdx.x] = 0;
}

// residual R = Y - conv_D(X_sparse); per-sample l2; zero hist/ccnt
__global__ void k_residual(const float* __restrict__ Y, const float* __restrict__ Wg,
                           const float* __restrict__ X) {
    __shared__ float syh[IMGPIX];
    __shared__ float sred[8];
    int s = blockIdx.x, tid = threadIdx.x;
    if (tid == 0) d_ccnt[s] = 0;
    int4* h4 = (int4*)&d_hist[s*NBINS];
    int4 z4 = make_int4(0,0,0,0);
    for (int i = tid; i < NBINS/4; i += 256) h4[i] = z4;
    for (int i = tid; i < IMGPIX; i += 256) syh[i] = 0.f;
    __syncthreads();
    int ns = d_nsup[s];
    if (tid < ns) {
        int pos = d_supp[s*KSEL + tid];
        if (pos >= 0) {
            float val = X[s*NPS + pos];
            int a = pos / SPP, rem = pos - a*SPP, u = rem / OH, v = rem - u*OH;
            const float* w = Wg + a*64;
            #pragma unroll
            for (int p = 0; p < 8; p++)
                #pragma unroll
                for (int q = 0; q < 8; q++)
                    atomicAdd(&syh[(u+p)*WW + v + q], val * w[p*8 + q]);
        }
    }
    __syncthreads();
    float e = 0.f;
    for (int i = tid; i < IMGPIX; i += 256) {
        float r = Y[s*IMGPIX + i] - syh[i];
        d_R[s*IMGPIX + i] = r;
        e += r*r;
    }
    for (int o = 16; o; o >>= 1) e += __shfl_down_sync(0xffffffffu, e, o);
    if ((tid & 31) == 0) sred[tid >> 5] = e;
    __syncthreads();
    if (tid < 32) {
        e = (tid < 8) ? sred[tid] : 0.f;
        for (int o = 4; o; o >>= 1) e += __shfl_down_sync(0xffffffffu, e, o);
        if (tid == 0) d_l2p[s] = e;
    }
}

// g[b,a,u,v] = sum_{p,q} R[b,u+p,v+q] * W[a,q,p]; fused |g| histogram + u16 key store.
// Tile: 8 atoms x 32 u-rows per block (A=8, U=8 per thread -> LDS:FMA balanced).
__global__ void __launch_bounds__(256) k_conv_g(const float* __restrict__ Wg) {
    __shared__ float shR[39*64 + 16];
    __shared__ float shW[64*8];       // [p*8+q][a]
    __shared__ int   shH[NBINS];
    int bid = blockIdx.x;
    int s   = bid >> 5;
    int rem = bid & 31;
    int grp = rem >> 1;
    int uc  = rem & 1;
    int ub  = uc * 32;
    int abase = grp * 8;
    int tid = threadIdx.x;

    for (int i = tid; i < NBINS; i += 256) shH[i] = 0;
    for (int i = tid; i < 39*64; i += 256) {
        int r = ub + (i >> 6);
        shR[i] = (r < HH) ? d_R[s*IMGPIX + r*WW + (i & 63)] : 0.f;
    }
    if (tid < 16) shR[39*64 + tid] = 0.f;
    for (int i = tid; i < 512; i += 256) {
        int a = i & 7, pq = i >> 3, p = pq >> 3, q = pq & 7;
        shW[pq*8 + a] = Wg[(abase + a)*64 + q*8 + p];
    }
    __syncthreads();

    int v  = tid & 63;
    int ty = tid >> 6;
    int u0 = ty * 8;

    ull acc[4][8];
    #pragma unroll
    for (int ap = 0; ap < 4; ap++)
        #pragma unroll
        for (int uu = 0; uu < 8; uu++) acc[ap][uu] = 0ull;

    #pragma unroll 1
    for (int p = 0; p < 8; p++) {
        #pragma unroll
        for (int q = 0; q < 8; q++) {
            ull w2[4];
            const ull* wrow = (const ull*)&shW[(p*8 + q)*8];
            #pragma unroll
            for (int ap = 0; ap < 4; ap++) w2[ap] = wrow[ap];
            #pragma unroll
            for (int uu = 0; uu < 8; uu++) {
                float r = shR[(u0 + uu + p)*64 + v + q];
                ull r2;
                asm("mov.b64 %0, {%1, %1};" : "=l"(r2) : "f"(r));
                #pragma unroll
                for (int ap = 0; ap < 4; ap++)
                    asm("fma.rn.f32x2 %0, %1, %2, %0;"
                        : "+l"(acc[ap][uu]) : "l"(w2[ap]), "l"(r2));
            }
        }
    }

    bool vok = (v < OH);
    #pragma unroll
    for (int uu = 0; uu < 8; uu++) {
        int u = ub + u0 + uu;
        if (vok && u < OH) {
            int rbase = u*OH + v;
            int base = s*NPS + abase*SPP + rbase;
            int hbase = s*NW32 + (grp*4)*SPP + rbase;
            #pragma unroll
            for (int ap = 0; ap < 4; ap++) {
                float lo, hi;
                asm("mov.b64 {%0, %1}, %2;" : "=f"(lo), "=f"(hi) : "l"(acc[ap][uu]));
                d_g[base + (2*ap)*SPP]   = lo;
                d_g[base + (2*ap+1)*SPP] = hi;
                unsigned klo = (__float_as_uint(lo) & 0x7fffffffu) >> 16;
                unsigned khi = (__float_as_uint(hi) & 0x7fffffffu) >> 16;
                d_gh[hbase + ap*SPP] = klo | (khi << 16);
                atomicAdd(&shH[(int)(klo >> 3)], 1);
                atomicAdd(&shH[(int)(khi >> 3)], 1);
            }
        }
    }
    __syncthreads();
    for (int i = tid; i < NBINS; i += 256)
        if (shH[i]) atomicAdd(&d_hist[s*NBINS + i], shH[i]);
}

// grid (52, 32): per-block redundant threshold; chunks 0..50 scan the u16 key
// stream (26.6 MB), fetching full g/X only for hits; chunk 51 appends support.
__global__ void __launch_bounds__(256) k_collect(const float* __restrict__ X) {
    __shared__ int wtmp[8];
    __shared__ int s_thr;
    int s = blockIdx.y, chunk = blockIdx.x, tid = threadIdx.x;

    const int* hist = &d_hist[s*NBINS];
    int seg = 0;
    #pragma unroll
    for (int j = 0; j < 16; j++) seg += hist[tid*16 + j];
    int ss = suffix_scan(seg, wtmp, 8);
    int low = ss - seg;
    if (ss >= 2*KSEL && low < 2*KSEL) {
        int cum = low;
        for (int j = 15; j >= 0; j--) {
            cum += hist[tid*16 + j];
            if (cum >= 2*KSEL) { s_thr = tid*16 + j; break; }
        }
    }
    __syncthreads();
    int thr = s_thr;

    if (chunk == 51) {
        unsigned thrbits = (unsigned)thr << 19;
        int ns = d_nsup[s];
        if (tid < ns) {
            int pos = d_supp[s*KSEL + tid];
            if (pos >= 0) {
                float gv = d_g[s*NPS + pos];
                if ((__float_as_uint(gv) & 0x7fffffffu) < thrbits) {
                    int idx = atomicAdd(&d_ccnt[s], 1);
                    if (idx < CAP) {
                        d_cpos[s*CAP + idx] = pos;
                        d_cg[s*CAP + idx]   = gv;
                        d_cx[s*CAP + idx]   = X[s*NPS + pos];
                    }
                }
            }
        }
        return;
    }

    unsigned thr16 = (unsigned)thr << 3;   // key16 >= thr<<3  <=>  bin >= thr
    const uint4* h4 = (const uint4*)&d_gh[s*NW32];
    int base = chunk * HCHUNK;
    int end = base + HCHUNK; if (end > NV16) end = NV16;
    int i0 = base + tid;

    #pragma unroll
    for (int dd = 0; dd < 4; dd++) {
        int i = i0 + dd*256;
        if (i < end) {
            uint4 w4 = h4[i];
            unsigned ws[4] = {w4.x, w4.y, w4.z, w4.w};
            #pragma unroll
            for (int wi = 0; wi < 4; wi++) {
                unsigned w = ws[wi];
                unsigned k0 = w & 0xffffu;
                unsigned k1 = w >> 16;
                if (k0 >= thr16 || k1 >= thr16) {
                    int j = i*4 + wi;           // u32 index within sample
                    int apg = j / SPP;
                    int r   = j - apg*SPP;
                    #pragma unroll
                    for (int half = 0; half < 2; half++) {
                        unsigned k = half ? k1 : k0;
                        if (k >= thr16) {
                            int pos = (2*apg + half)*SPP + r;
                            float gv = d_g[s*NPS + pos];
                            int idx = atomicAdd(&d_ccnt[s], 1);
                            if (idx < CAP) {
                                d_cpos[s*CAP + idx] = pos;
                                d_cg[s*CAP + idx]   = gv;
                                d_cx[s*CAP + idx]   = X[s*NPS + pos];
                            }
                        }
                    }
                }
            }
        }
    }
}

// one block per (alpha, sample): exact top-256 via 12-bit radix-select on unique
// 51-bit keys (abs<<19 | ~pos); then sparse reconstruction + err.
__global__ void __launch_bounds__(512) k_attempt(const float* __restrict__ Y,
                                                 const float* __restrict__ Wg) {
    __shared__ ull   skey[CAP];
    __shared__ float sval[CAP];
    __shared__ unsigned aux[NBINS];   // digit hist, later syh
    __shared__ int   wtmp[16];
    __shared__ ull   s_prefix, s_T;
    __shared__ int   s_m, s_done, s_cnt;
    __shared__ float sred[16];

    int ka = blockIdx.x, s = blockIdx.y, tid = threadIdx.x;
    float alpha = 1.0f / (float)(1 << ka);
    int n = d_ccnt[s]; if (n > CAP) n = CAP;

    for (int i = tid; i < n; i += 512) {
        int pos = d_cpos[s*CAP + i];
        float val = d_cx[s*CAP + i] + alpha * d_cg[s*CAP + i];
        unsigned ab = __float_as_uint(val) & 0x7fffffffu;
        skey[i] = ((ull)ab << 19) | (unsigned)((~pos) & 0x7ffff);
        sval[i] = val;
    }
    if (tid == 0) { s_prefix = 0ull; s_m = KSEL; s_done = (n <= KSEL) ? 1 : 0; s_T = 1ull; }

    for (int lvl = 0; lvl < 5; lvl++) {
        __syncthreads();
        int done = s_done; ull pref = s_prefix; int m = s_m;
        int shift = 48 - 12*lvl;
        if (!done) {
            for (int i = tid; i < NBINS; i += 512) aux[i] = 0u;
            __syncthreads();
            ull himask = ~(((ull)1 << (shift + 12)) - 1);
            for (int i = tid; i < n; i += 512) {
                ull k = skey[i];
                if ((k & himask) == pref)
                    atomicAdd(&aux[(unsigned)((k >> shift) & 0xFFF)], 1u);
            }
            __syncthreads();
            int seg = 0;
            #pragma unroll
            for (int j = 0; j < 8; j++) seg += (int)aux[tid*8 + j];
            int ss = suffix_scan(seg, wtmp, 16);
            int low = ss - seg;
            if (ss >= m && low < m) {
                int cum = low, b = tid*8, h_b = 0;
                for (int j = 7; j >= 0; j--) {
                    int c = (int)aux[tid*8 + j];
                    cum += c;
                    if (cum >= m) { b = tid*8 + j; h_b = c; break; }
                }
                ull npref = pref | ((ull)b << shift);
                if (cum == m || shift == 0) { s_T = npref; s_done = 1; }
                else { s_prefix = npref; s_m = m - (cum - h_b); }
            }
        } else {
            __syncthreads();
        }
    }
    __syncthreads();
    ull T = s_T;

    int selbase = (ka*BATCH + s)*KSEL;
    if (tid < KSEL) d_selp[selbase + tid] = -1;
    for (int i = tid; i < IMGPIX; i += 512) aux[i] = 0u;
    if (tid == 0) s_cnt = 0;
    __syncthreads();

    float* syh = (float*)aux;
    for (int i = tid; i < n; i += 512) {
        ull k = skey[i];
        if (k >= T) {
            int slot = atomicAdd(&s_cnt, 1);
            int pos = (int)((~(unsigned)k) & 0x7ffff);
            float val = sval[i];
            d_selp[selbase + slot] = pos;
            d_selv[selbase + slot] = val;
            int a = pos / SPP, rem2 = pos - a*SPP, u = rem2 / OH, vv = rem2 - u*OH;
            const float* w = Wg + a*64;
            #pragma unroll
            for (int p = 0; p < 8; p++)
                #pragma unroll
                for (int q = 0; q < 8; q++)
                    atomicAdd(&syh[(u+p)*WW + vv + q], val * w[p*8 + q]);
        }
    }
    __syncthreads();
    float e = 0.f;
    for (int i = tid; i < IMGPIX; i += 512) {
        float d = Y[s*IMGPIX + i] - syh[i];
        e += d*d;
    }
    for (int o = 16; o; o >>= 1) e += __shfl_down_sync(0xffffffffu, e, o);
    if ((tid & 31) == 0) sred[tid >> 5] = e;
    __syncthreads();
    if (tid < 32) {
        e = (tid < 16) ? sred[tid] : 0.f;
        for (int o = 8; o; o >>= 1) e += __shfl_down_sync(0xffffffffu, e, o);
        if (tid == 0) d_errp[ka*BATCH + s] = e;
    }
}

// commit: parallel redundant alpha choice, scatter-update X + support
__global__ void k_commit(float* __restrict__ X) {
    __shared__ float serr[NAL];
    __shared__ float sl2;
    __shared__ int sc;
    int s = blockIdx.x, tid = threadIdx.x;
    if (tid < NAL) {
        float e = 0.f;
        for (int s2 = 0; s2 < BATCH; s2++) e += d_errp[tid*BATCH + s2];
        serr[tid] = e;
    }
    if (tid == 32) {
        float l2 = 0.f;
        for (int s2 = 0; s2 < BATCH; s2++) l2 += d_l2p[s2];
        sl2 = l2;
    }
    __syncthreads();
    if (tid == 0) {
        int c = NAL - 1;
        for (int k = 0; k < NAL; k++)
            if (serr[k] < sl2) { c = k; break; }
        sc = c;
    }
    int ns = d_nsup[s];
    if (tid < ns) {
        int p = d_supp[s*KSEL + tid];
        if (p >= 0) X[s*NPS + p] = 0.f;
    }
    __syncthreads();
    int c = sc;
    int pos = d_selp[(c*BATCH + s)*KSEL + tid];
    float val = d_selv[(c*BATCH + s)*KSEL + tid];
    if (pos >= 0) X[s*NPS + pos] = val;
    d_supp[s*KSEL + tid] = pos;
    if (tid == 0) d_nsup[s] = KSEL;
}

// ---------------- launch ----------------
extern "C" void kernel_launch(void* const* d_in, const int* in_sizes, int n_in,
                              void* d_out, int out_size) {
    const float* Y  = (const float*)d_in[0];
    const float* Wg = (const float*)d_in[1];
    float* X = (float*)d_out;

    k_init<<<2048, 256>>>(X);
    for (int it = 0; it < 3; it++) {
        k_residual<<<BATCH, 256>>>(Y, Wg, X);
        k_conv_g<<<1024, 256>>>(Wg);
        k_collect<<<dim3(52, BATCH), 256>>>(X);   // 4th launch -> profiled
        k_attempt<<<dim3(NAL, BATCH), 512>>>(Y, Wg);
        k_commit<<<BATCH, KSEL>>>(X);
    }
}